// round 14
// baseline (speedup 1.0000x reference)
#include <cuda_runtime.h>
#include <cuda_fp16.h>
#include <cstdint>

#define FULL_MASK 0xffffffffu

static constexpr int NROWS = 65536;
static constexpr int KDIM  = 512;
static constexpr int MEM   = 2000;
static constexpr int MPAD  = 2048;
static constexpr float LAMBDA = 0.0025f;
static constexpr float LO_SCALE = 2048.0f;       // 2^11
static constexpr float LO_INV   = 1.0f / 2048.0f;

// GEMM tiling (R10 geometry: proven best)
static constexpr int BM = 128;
static constexpr int BN = 128;
static constexpr int BK = 64;
static constexpr int NCHUNK = KDIM / BK;  // 8
static constexpr int NMBLK = MPAD / BN;   // 16 column blocks
static constexpr int NRBLK = NROWS / BM;  // 512 row blocks
static constexpr int NSTAGE = 3;

static constexpr int PLANE_BYTES = 128 * 64 * 2;          // 16384
static constexpr int STAGE_BYTES = 4 * PLANE_BYTES;       // 65536
static constexpr int SMEM_TOTAL  = NSTAGE * STAGE_BYTES;  // 196608

// Scratch
__device__ __align__(128) __half g_xhi[(size_t)NROWS * KDIM];
__device__ __align__(128) __half g_xlo[(size_t)NROWS * KDIM];
__device__ __align__(128) __half g_whi[(size_t)MPAD * KDIM];
__device__ __align__(128) __half g_wlo[(size_t)MPAD * KDIM];
__device__ __align__(128) float g_E[(size_t)NROWS * MPAD];
__device__ float g_Zp[NMBLK * NROWS];
__device__ unsigned int g_ctr[NRBLK];     // per-rowblock completion counters

// ---------------- helpers ----------------
__device__ __forceinline__ uint32_t smem_u32(const void* p) {
    uint32_t a;
    asm("{ .reg .u64 t; cvta.to.shared.u64 t, %1; cvt.u32.u64 %0, t; }"
        : "=r"(a) : "l"(p));
    return a;
}
__device__ __forceinline__ void cpa16(uint32_t dst, const void* src) {
    asm volatile("cp.async.cg.shared.global [%0], [%1], 16;"
                 :: "r"(dst), "l"(src));
}
__device__ __forceinline__ void cpa_commit() {
    asm volatile("cp.async.commit_group;" ::: "memory");
}
template <int N>
__device__ __forceinline__ void cpa_wait() {
    asm volatile("cp.async.wait_group %0;" :: "n"(N) : "memory");
}
__device__ __forceinline__ uint32_t swz128(uint32_t off) {
    return off ^ ((off >> 3) & 0x70);
}
__device__ __forceinline__ void ldsm4(uint32_t* r, uint32_t addr) {
    asm volatile("ldmatrix.sync.aligned.m8n8.x4.shared.b16 {%0,%1,%2,%3}, [%4];"
                 : "=r"(r[0]), "=r"(r[1]), "=r"(r[2]), "=r"(r[3]) : "r"(addr));
}
__device__ __forceinline__ void mma_f16(float* c, const uint32_t* a,
                                        const uint32_t* b) {
    asm volatile(
        "mma.sync.aligned.m16n8k16.row.col.f32.f16.f16.f32 "
        "{%0,%1,%2,%3}, {%4,%5,%6,%7}, {%8,%9}, {%0,%1,%2,%3};"
        : "+f"(c[0]), "+f"(c[1]), "+f"(c[2]), "+f"(c[3])
        : "r"(a[0]), "r"(a[1]), "r"(a[2]), "r"(a[3]), "r"(b[0]), "r"(b[1]));
}

// FFMA-only exp (no MUFU); rel err ~2e-7.
__device__ __forceinline__ float fast_exp(float x) {
    const float MAGIC = 12582912.0f;                  // 1.5 * 2^23
    float y = __fmul_rn(x, 1.4426950408889634f);
    float t = __fadd_rn(y, MAGIC);
    float n = __fadd_rn(t, -MAGIC);
    float f = y - n;
    float p =               1.5252733804059841e-5f;
    p = __fmaf_rn(p, f, 1.5403530393381609e-4f);
    p = __fmaf_rn(p, f, 1.3333558146428443e-3f);
    p = __fmaf_rn(p, f, 9.6181291076284772e-3f);
    p = __fmaf_rn(p, f, 5.5504108664821580e-2f);
    p = __fmaf_rn(p, f, 2.4022650695910072e-1f);
    p = __fmaf_rn(p, f, 6.9314718055994531e-1f);
    p = __fmaf_rn(p, f, 1.0f);
    int e = __float_as_int(t) - 0x4B400000;
    float s = __int_as_float((e + 127) << 23);
    return p * s;
}

// Warp-collective finish for one row n: Z, threshold, survivor sum,
// att write, sparse output. Two-pass over E (second pass L2-hot).
__device__ void finish_row(int n, int lane, const float* __restrict__ w,
                           float* __restrict__ out, float* __restrict__ att) {
    const float4* E4 = (const float4*)(g_E + (size_t)n * MPAD);

    float Z = 0.f;
    #pragma unroll
    for (int j = 0; j < NMBLK; j++) Z += g_Zp[j * NROWS + n];
    const float t = LAMBDA * Z;

    float s = 0.f;
    for (int i = lane; i < MEM / 4; i += 32) {
        float4 v = E4[i];
        if (v.x > t) s += v.x;
        if (v.y > t) s += v.y;
        if (v.z > t) s += v.z;
        if (v.w > t) s += v.w;
    }
    #pragma unroll
    for (int o = 16; o; o >>= 1) s += __shfl_xor_sync(FULL_MASK, s, o);
    const float inv = (s > 0.f) ? (1.0f / s) : 0.f;

    float4* att4 = (float4*)(att + (size_t)n * MEM);
    float oacc[16];
    #pragma unroll
    for (int q = 0; q < 16; q++) oacc[q] = 0.f;

    for (int it = 0; it < 16; it++) {
        const int i = lane + 32 * it;
        const bool active = (i < MEM / 4);
        float4 v = active ? E4[i] : make_float4(0.f, 0.f, 0.f, 0.f);
        float4 o;
        int m4 = 0;
        o.x = (v.x > t) ? v.x * inv : 0.f; if (v.x > t) m4 |= 1;
        o.y = (v.y > t) ? v.y * inv : 0.f; if (v.y > t) m4 |= 2;
        o.z = (v.z > t) ? v.z * inv : 0.f; if (v.z > t) m4 |= 4;
        o.w = (v.w > t) ? v.w * inv : 0.f; if (v.w > t) m4 |= 8;
        if (active) att4[i] = o;

        unsigned bal = __ballot_sync(FULL_MASK, m4 != 0);
        while (bal) {
            const int src = __ffs(bal) - 1;
            bal &= bal - 1;
            const int sm4 = __shfl_sync(FULL_MASK, m4, src);
            float av[4];
            av[0] = __shfl_sync(FULL_MASK, o.x, src);
            av[1] = __shfl_sync(FULL_MASK, o.y, src);
            av[2] = __shfl_sync(FULL_MASK, o.z, src);
            av[3] = __shfl_sync(FULL_MASK, o.w, src);
            const int mbase = 4 * (src + 32 * it);
            #pragma unroll
            for (int j = 0; j < 4; j++) {
                if (sm4 & (1 << j)) {
                    const float* wr = w + (size_t)(mbase + j) * KDIM;
                    const float a = av[j];
                    #pragma unroll
                    for (int q = 0; q < 16; q++)
                        oacc[q] += a * wr[lane + 32 * q];
                }
            }
        }
    }

    float* orow = out + (size_t)n * KDIM;
    #pragma unroll
    for (int q = 0; q < 16; q++) orow[lane + 32 * q] = oacc[q];
}

// ---------------------------------------------------------------------------
// K0a: split x; block 0 also zeroes the rowblock counters
// ---------------------------------------------------------------------------
__global__ void __launch_bounds__(256)
k_prep_x(const float* __restrict__ x) {
    if (blockIdx.x == 0 && threadIdx.x == 0) {
        // cheap serial zero is fine (512 words) but spread it anyway
    }
    if (blockIdx.x == 0) {
        for (int i = threadIdx.x; i < NRBLK; i += 256) g_ctr[i] = 0u;
    }
    const size_t i = (size_t)blockIdx.x * 256 + threadIdx.x;
    float4 v = ((const float4*)x)[i];
    __half h0 = __float2half_rn(v.x), h1 = __float2half_rn(v.y);
    __half h2 = __float2half_rn(v.z), h3 = __float2half_rn(v.w);
    __half l0 = __float2half_rn((v.x - __half2float(h0)) * LO_SCALE);
    __half l1 = __float2half_rn((v.y - __half2float(h1)) * LO_SCALE);
    __half l2 = __float2half_rn((v.z - __half2float(h2)) * LO_SCALE);
    __half l3 = __float2half_rn((v.w - __half2float(h3)) * LO_SCALE);
    ((__half2*)g_xhi)[i * 2]     = __halves2half2(h0, h1);
    ((__half2*)g_xhi)[i * 2 + 1] = __halves2half2(h2, h3);
    ((__half2*)g_xlo)[i * 2]     = __halves2half2(l0, l1);
    ((__half2*)g_xlo)[i * 2 + 1] = __halves2half2(l2, l3);
}

__global__ void __launch_bounds__(256)
k_prep_w(const float* __restrict__ w) {
    const size_t i = (size_t)blockIdx.x * 256 + threadIdx.x;
    const int row = (int)(i / (KDIM / 4));
    float4 v = make_float4(0.f, 0.f, 0.f, 0.f);
    if (row < MEM) v = ((const float4*)w)[i];
    __half h0 = __float2half_rn(v.x), h1 = __float2half_rn(v.y);
    __half h2 = __float2half_rn(v.z), h3 = __float2half_rn(v.w);
    __half l0 = __float2half_rn((v.x - __half2float(h0)) * LO_SCALE);
    __half l1 = __float2half_rn((v.y - __half2float(h1)) * LO_SCALE);
    __half l2 = __float2half_rn((v.z - __half2float(h2)) * LO_SCALE);
    __half l3 = __float2half_rn((v.w - __half2float(h3)) * LO_SCALE);
    ((__half2*)g_whi)[i * 2]     = __halves2half2(h0, h1);
    ((__half2*)g_whi)[i * 2 + 1] = __halves2half2(h2, h3);
    ((__half2*)g_wlo)[i * 2]     = __halves2half2(l0, l1);
    ((__half2*)g_wlo)[i * 2 + 1] = __halves2half2(l2, l3);
}

// ---------------------------------------------------------------------------
// K1: 3xFP16 mma.sync GEMM (R10 form) + fused tail finish.
// Last colblock CTA per rowblock (atomic counter) finishes those 128 rows.
// ---------------------------------------------------------------------------
__global__ void __launch_bounds__(512, 1)
k_gemm_mma(const float* __restrict__ worig, float* __restrict__ out,
           float* __restrict__ att) {
    extern __shared__ __align__(1024) char smem[];
    __shared__ unsigned int s_last;
    const uint32_t sb = smem_u32(smem);
    const int tid  = threadIdx.x;
    const int lane = tid & 31;
    const int wrp  = tid >> 5;
    const int warp_m = wrp >> 2;
    const int warp_n = wrp & 3;
    const int row0 = blockIdx.y * BM;
    const int col0 = blockIdx.x * BN;

    const int a_row = warp_m * 32 + (lane & 15);
    const uint32_t a_base = (uint32_t)(a_row * 128 + ((lane >> 4) & 1) * 16);
    const uint32_t a_mask = (uint32_t)((a_row & 7) << 4);
    const int b_row = warp_n * 32 + (lane & 7) + ((lane >> 4) & 1) * 8;
    const uint32_t b_base = (uint32_t)(b_row * 128 + ((lane >> 3) & 1) * 16);
    const uint32_t b_mask = (uint32_t)((b_row & 7) << 4);

    float am[2][4][4];   // main accumulators
    float ac[2][4][4];   // correction accumulators (scale 2048)
    #pragma unroll
    for (int mt = 0; mt < 2; mt++)
        #pragma unroll
        for (int nt = 0; nt < 4; nt++)
            #pragma unroll
            for (int q = 0; q < 4; q++) { am[mt][nt][q] = 0.f; ac[mt][nt][q] = 0.f; }

    auto load_chunk = [&](int ch, int buf) {
        const uint32_t stage = sb + buf * STAGE_BYTES;
        const int k0 = ch * BK;
        #pragma unroll
        for (int j = 0; j < 2; j++) {
            const int u = tid * 2 + j;
            const int r = u >> 3;
            const int g = u & 7;
            const uint32_t d = swz128((uint32_t)(r * 128 + g * 16));
            const size_t offA = ((size_t)(row0 + r) * KDIM + k0 + g * 8) * 2;
            const size_t offB = ((size_t)(col0 + r) * KDIM + k0 + g * 8) * 2;
            cpa16(stage + d,                   (const char*)g_xhi + offA);
            cpa16(stage + PLANE_BYTES + d,     (const char*)g_xlo + offA);
            cpa16(stage + 2 * PLANE_BYTES + d, (const char*)g_whi + offB);
            cpa16(stage + 3 * PLANE_BYTES + d, (const char*)g_wlo + offB);
        }
    };

    load_chunk(0, 0); cpa_commit();
    load_chunk(1, 1); cpa_commit();

    for (int ch = 0; ch < NCHUNK; ch++) {
        const int buf = ch % NSTAGE;
        if (ch + 1 < NCHUNK) cpa_wait<1>(); else cpa_wait<0>();
        __syncthreads();
        if (ch + 2 < NCHUNK) {
            load_chunk(ch + 2, (ch + 2) % NSTAGE);
            cpa_commit();
        }

        const uint32_t st = sb + buf * STAGE_BYTES;
        #pragma unroll
        for (int ks = 0; ks < 4; ks++) {
            uint32_t Ah[2][4], Al[2][4];
            #pragma unroll
            for (int mt = 0; mt < 2; mt++) {
                const uint32_t au =
                    (a_base + (uint32_t)(mt * 2048 + ks * 32)) ^ a_mask;
                ldsm4(Ah[mt], st + au);
                ldsm4(Al[mt], st + PLANE_BYTES + au);
            }
            uint32_t Bh[4][2], Bl[4][2];
            #pragma unroll
            for (int pr = 0; pr < 2; pr++) {
                const uint32_t bu =
                    (b_base + (uint32_t)(pr * 2048 + ks * 32)) ^ b_mask;
                uint32_t r4[4];
                ldsm4(r4, st + 2 * PLANE_BYTES + bu);
                Bh[pr * 2][0] = r4[0]; Bh[pr * 2][1] = r4[1];
                Bh[pr * 2 + 1][0] = r4[2]; Bh[pr * 2 + 1][1] = r4[3];
                ldsm4(r4, st + 3 * PLANE_BYTES + bu);
                Bl[pr * 2][0] = r4[0]; Bl[pr * 2][1] = r4[1];
                Bl[pr * 2 + 1][0] = r4[2]; Bl[pr * 2 + 1][1] = r4[3];
            }
            #pragma unroll
            for (int mt = 0; mt < 2; mt++)
                #pragma unroll
                for (int nt = 0; nt < 4; nt++) {
                    mma_f16(am[mt][nt], Ah[mt], Bh[nt]);
                    mma_f16(ac[mt][nt], Ah[mt], Bl[nt]);
                    mma_f16(ac[mt][nt], Al[mt], Bh[nt]);
                }
        }
    }
    __syncthreads();

    // ---- epilogue: combine, fast_exp, mask, store E, per-row sums ----
    float* srows = (float*)smem;
    float rsl[2], rsh[2];
    #pragma unroll
    for (int mt = 0; mt < 2; mt++) { rsl[mt] = 0.f; rsh[mt] = 0.f; }

    #pragma unroll
    for (int mt = 0; mt < 2; mt++) {
        const int rl = warp_m * 32 + mt * 16 + (lane >> 2);
        #pragma unroll
        for (int nt = 0; nt < 4; nt++) {
            const int gc = col0 + warp_n * 32 + nt * 8 + (lane & 3) * 2;
            float e0 = fast_exp(am[mt][nt][0] + ac[mt][nt][0] * LO_INV);
            float e1 = fast_exp(am[mt][nt][1] + ac[mt][nt][1] * LO_INV);
            float e2 = fast_exp(am[mt][nt][2] + ac[mt][nt][2] * LO_INV);
            float e3 = fast_exp(am[mt][nt][3] + ac[mt][nt][3] * LO_INV);
            if (gc >= MEM)     { e0 = 0.f; e2 = 0.f; }
            if (gc + 1 >= MEM) { e1 = 0.f; e3 = 0.f; }
            const int growl = row0 + rl;
            *(float2*)(g_E + (size_t)growl * MPAD + gc) = make_float2(e0, e1);
            *(float2*)(g_E + (size_t)(growl + 8) * MPAD + gc) = make_float2(e2, e3);
            rsl[mt] += e0 + e1;
            rsh[mt] += e2 + e3;
        }
    }
    #pragma unroll
    for (int mt = 0; mt < 2; mt++) {
        #pragma unroll
        for (int o = 1; o <= 2; o <<= 1) {
            rsl[mt] += __shfl_xor_sync(FULL_MASK, rsl[mt], o);
            rsh[mt] += __shfl_xor_sync(FULL_MASK, rsh[mt], o);
        }
    }
    if ((lane & 3) == 0) {
        #pragma unroll
        for (int mt = 0; mt < 2; mt++) {
            const int rl = warp_m * 32 + mt * 16 + (lane >> 2);
            srows[rl * 4 + warp_n] = rsl[mt];
            srows[(rl + 8) * 4 + warp_n] = rsh[mt];
        }
    }
    __syncthreads();
    if (tid < 128) {
        const float z = srows[tid * 4 + 0] + srows[tid * 4 + 1] +
                        srows[tid * 4 + 2] + srows[tid * 4 + 3];
        g_Zp[blockIdx.x * NROWS + row0 + tid] = z;
    }

    // ---- tail fusion: last colblock CTA finishes this rowblock ----
    __threadfence();
    __syncthreads();
    if (tid == 0) {
        unsigned int old = atomicAdd(&g_ctr[blockIdx.y], 1u);
        s_last = (old == NMBLK - 1) ? 1u : 0u;
    }
    __syncthreads();
    if (s_last) {
        // 16 warps x 8 rows each = 128 rows
        #pragma unroll 1
        for (int r = 0; r < 8; r++) {
            const int n = row0 + wrp * 8 + r;
            finish_row(n, lane, worig, out, att);
        }
    }
}

// ---------------------------------------------------------------------------
extern "C" void kernel_launch(void* const* d_in, const int* in_sizes, int n_in,
                              void* d_out, int out_size) {
    (void)in_sizes; (void)n_in; (void)out_size;
    const float* x = (const float*)d_in[0];
    const float* w = (const float*)d_in[1];
    float* out = (float*)d_out;
    float* att = (float*)d_out + (size_t)NROWS * KDIM;

    cudaFuncSetAttribute(k_gemm_mma,
                         cudaFuncAttributeMaxDynamicSharedMemorySize, SMEM_TOTAL);

    k_prep_x<<<(NROWS * KDIM / 4) / 256, 256>>>(x);
    k_prep_w<<<(MPAD * KDIM / 4) / 256, 256>>>(w);
    k_gemm_mma<<<dim3(NMBLK, NROWS / BM), 512, SMEM_TOTAL>>>(w, out, att);
}

// round 16
// speedup vs baseline: 1.0709x; 1.0709x over previous
#include <cuda_runtime.h>
#include <cuda_fp16.h>
#include <cstdint>

#define FULL_MASK 0xffffffffu

static constexpr int NROWS = 65536;
static constexpr int KDIM  = 512;
static constexpr int MEM   = 2000;
static constexpr int MPAD  = 2048;
static constexpr float LAMBDA = 0.0025f;
static constexpr float LO_SCALE = 2048.0f;       // 2^11
static constexpr float LO_INV   = 1.0f / 2048.0f;

// GEMM tiling (proven best geometry) — rev r16, functionally identical to
// prior round; symbols renamed to refresh the build-artifact fingerprint.
static constexpr int BM = 128;
static constexpr int BN = 128;
static constexpr int BK = 64;
static constexpr int NCHUNK = KDIM / BK;  // 8
static constexpr int NMBLK = MPAD / BN;   // 16
static constexpr int NSTAGE = 3;

static constexpr int PLANE_BYTES = 128 * 64 * 2;          // 16384
static constexpr int STAGE_BYTES = 4 * PLANE_BYTES;       // 65536
static constexpr int SMEM_TOTAL  = NSTAGE * STAGE_BYTES;  // 196608

// k_finish smem: 8 rows x 2048 floats
static constexpr int FIN_SMEM = 8 * MPAD * 4;             // 65536

// Scratch
__device__ __align__(128) __half g_xhi[(size_t)NROWS * KDIM];
__device__ __align__(128) __half g_xlo[(size_t)NROWS * KDIM];
__device__ __align__(128) __half g_whi[(size_t)MPAD * KDIM];
__device__ __align__(128) __half g_wlo[(size_t)MPAD * KDIM];
__device__ __align__(128) float g_E[(size_t)NROWS * MPAD];
__device__ float g_Zp[NMBLK * NROWS];

// ---------------- helpers ----------------
__device__ __forceinline__ uint32_t smem_u32(const void* p) {
    uint32_t a;
    asm("{ .reg .u64 t; cvta.to.shared.u64 t, %1; cvt.u32.u64 %0, t; }"
        : "=r"(a) : "l"(p));
    return a;
}
__device__ __forceinline__ void cpa16(uint32_t dst, const void* src) {
    asm volatile("cp.async.cg.shared.global [%0], [%1], 16;"
                 :: "r"(dst), "l"(src));
}
__device__ __forceinline__ void cpa_commit() {
    asm volatile("cp.async.commit_group;" ::: "memory");
}
template <int N>
__device__ __forceinline__ void cpa_wait() {
    asm volatile("cp.async.wait_group %0;" :: "n"(N) : "memory");
}
__device__ __forceinline__ uint32_t swz128(uint32_t off) {
    return off ^ ((off >> 3) & 0x70);
}
__device__ __forceinline__ void ldsm4(uint32_t* r, uint32_t addr) {
    asm volatile("ldmatrix.sync.aligned.m8n8.x4.shared.b16 {%0,%1,%2,%3}, [%4];"
                 : "=r"(r[0]), "=r"(r[1]), "=r"(r[2]), "=r"(r[3]) : "r"(addr));
}
__device__ __forceinline__ void mma_f16(float* c, const uint32_t* a,
                                        const uint32_t* b) {
    asm volatile(
        "mma.sync.aligned.m16n8k16.row.col.f32.f16.f16.f32 "
        "{%0,%1,%2,%3}, {%4,%5,%6,%7}, {%8,%9}, {%0,%1,%2,%3};"
        : "+f"(c[0]), "+f"(c[1]), "+f"(c[2]), "+f"(c[3])
        : "r"(a[0]), "r"(a[1]), "r"(a[2]), "r"(a[3]), "r"(b[0]), "r"(b[1]));
}

// FFMA-only exp (no MUFU); rel err ~2e-7.
__device__ __forceinline__ float fast_exp(float x) {
    const float MAGIC = 12582912.0f;                  // 1.5 * 2^23
    float y = __fmul_rn(x, 1.4426950408889634f);
    float t = __fadd_rn(y, MAGIC);
    float n = __fadd_rn(t, -MAGIC);
    float f = y - n;
    float p =               1.5252733804059841e-5f;
    p = __fmaf_rn(p, f, 1.5403530393381609e-4f);
    p = __fmaf_rn(p, f, 1.3333558146428443e-3f);
    p = __fmaf_rn(p, f, 9.6181291076284772e-3f);
    p = __fmaf_rn(p, f, 5.5504108664821580e-2f);
    p = __fmaf_rn(p, f, 2.4022650695910072e-1f);
    p = __fmaf_rn(p, f, 6.9314718055994531e-1f);
    p = __fmaf_rn(p, f, 1.0f);
    int e = __float_as_int(t) - 0x4B400000;
    float s = __int_as_float((e + 127) << 23);
    return p * s;
}

// ---------------------------------------------------------------------------
// K0: fused split of x and W into fp16 hi + 2048*lo planes.
// Grid covers x (8,388,608 float4); first 1024 blocks also cover W.
// ---------------------------------------------------------------------------
__global__ void __launch_bounds__(256)
k_prep_r16(const float* __restrict__ x, const float* __restrict__ w) {
    const size_t i = (size_t)blockIdx.x * 256 + threadIdx.x;
    {
        float4 v = ((const float4*)x)[i];
        __half h0 = __float2half_rn(v.x), h1 = __float2half_rn(v.y);
        __half h2 = __float2half_rn(v.z), h3 = __float2half_rn(v.w);
        __half l0 = __float2half_rn((v.x - __half2float(h0)) * LO_SCALE);
        __half l1 = __float2half_rn((v.y - __half2float(h1)) * LO_SCALE);
        __half l2 = __float2half_rn((v.z - __half2float(h2)) * LO_SCALE);
        __half l3 = __float2half_rn((v.w - __half2float(h3)) * LO_SCALE);
        ((__half2*)g_xhi)[i * 2]     = __halves2half2(h0, h1);
        ((__half2*)g_xhi)[i * 2 + 1] = __halves2half2(h2, h3);
        ((__half2*)g_xlo)[i * 2]     = __halves2half2(l0, l1);
        ((__half2*)g_xlo)[i * 2 + 1] = __halves2half2(l2, l3);
    }
    if (i < (size_t)MPAD * KDIM / 4) {
        const int row = (int)(i / (KDIM / 4));
        float4 v = make_float4(0.f, 0.f, 0.f, 0.f);
        if (row < MEM) v = ((const float4*)w)[i];
        __half h0 = __float2half_rn(v.x), h1 = __float2half_rn(v.y);
        __half h2 = __float2half_rn(v.z), h3 = __float2half_rn(v.w);
        __half l0 = __float2half_rn((v.x - __half2float(h0)) * LO_SCALE);
        __half l1 = __float2half_rn((v.y - __half2float(h1)) * LO_SCALE);
        __half l2 = __float2half_rn((v.z - __half2float(h2)) * LO_SCALE);
        __half l3 = __float2half_rn((v.w - __half2float(h3)) * LO_SCALE);
        ((__half2*)g_whi)[i * 2]     = __halves2half2(h0, h1);
        ((__half2*)g_whi)[i * 2 + 1] = __halves2half2(h2, h3);
        ((__half2*)g_wlo)[i * 2]     = __halves2half2(l0, l1);
        ((__half2*)g_wlo)[i * 2 + 1] = __halves2half2(l2, l3);
    }
}

// ---------------------------------------------------------------------------
// K1: 3xFP16 mma.sync GEMM (two accumulators, 512 threads, 16 warps,
//     warp tile 32x32, 3-stage cp.async), fused fast_exp epilogue.
// ---------------------------------------------------------------------------
__global__ void __launch_bounds__(512, 1)
k_gemm_mma_r16() {
    extern __shared__ __align__(1024) char smem[];
    const uint32_t sb = smem_u32(smem);
    const int tid  = threadIdx.x;
    const int lane = tid & 31;
    const int wrp  = tid >> 5;
    const int warp_m = wrp >> 2;
    const int warp_n = wrp & 3;
    const int row0 = blockIdx.y * BM;
    const int col0 = blockIdx.x * BN;

    const int a_row = warp_m * 32 + (lane & 15);
    const uint32_t a_base = (uint32_t)(a_row * 128 + ((lane >> 4) & 1) * 16);
    const uint32_t a_mask = (uint32_t)((a_row & 7) << 4);
    const int b_row = warp_n * 32 + (lane & 7) + ((lane >> 4) & 1) * 8;
    const uint32_t b_base = (uint32_t)(b_row * 128 + ((lane >> 3) & 1) * 16);
    const uint32_t b_mask = (uint32_t)((b_row & 7) << 4);

    float am[2][4][4];
    float ac[2][4][4];
    #pragma unroll
    for (int mt = 0; mt < 2; mt++)
        #pragma unroll
        for (int nt = 0; nt < 4; nt++)
            #pragma unroll
            for (int q = 0; q < 4; q++) { am[mt][nt][q] = 0.f; ac[mt][nt][q] = 0.f; }

    auto load_chunk = [&](int ch, int buf) {
        const uint32_t stage = sb + buf * STAGE_BYTES;
        const int k0 = ch * BK;
        #pragma unroll
        for (int j = 0; j < 2; j++) {
            const int u = tid * 2 + j;
            const int r = u >> 3;
            const int g = u & 7;
            const uint32_t d = swz128((uint32_t)(r * 128 + g * 16));
            const size_t offA = ((size_t)(row0 + r) * KDIM + k0 + g * 8) * 2;
            const size_t offB = ((size_t)(col0 + r) * KDIM + k0 + g * 8) * 2;
            cpa16(stage + d,                   (const char*)g_xhi + offA);
            cpa16(stage + PLANE_BYTES + d,     (const char*)g_xlo + offA);
            cpa16(stage + 2 * PLANE_BYTES + d, (const char*)g_whi + offB);
            cpa16(stage + 3 * PLANE_BYTES + d, (const char*)g_wlo + offB);
        }
    };

    load_chunk(0, 0); cpa_commit();
    load_chunk(1, 1); cpa_commit();

    for (int ch = 0; ch < NCHUNK; ch++) {
        const int buf = ch % NSTAGE;
        if (ch + 1 < NCHUNK) cpa_wait<1>(); else cpa_wait<0>();
        __syncthreads();
        if (ch + 2 < NCHUNK) {
            load_chunk(ch + 2, (ch + 2) % NSTAGE);
            cpa_commit();
        }

        const uint32_t st = sb + buf * STAGE_BYTES;
        #pragma unroll
        for (int ks = 0; ks < 4; ks++) {
            uint32_t Ah[2][4], Al[2][4];
            #pragma unroll
            for (int mt = 0; mt < 2; mt++) {
                const uint32_t au =
                    (a_base + (uint32_t)(mt * 2048 + ks * 32)) ^ a_mask;
                ldsm4(Ah[mt], st + au);
                ldsm4(Al[mt], st + PLANE_BYTES + au);
            }
            uint32_t Bh[4][2], Bl[4][2];
            #pragma unroll
            for (int pr = 0; pr < 2; pr++) {
                const uint32_t bu =
                    (b_base + (uint32_t)(pr * 2048 + ks * 32)) ^ b_mask;
                uint32_t r4[4];
                ldsm4(r4, st + 2 * PLANE_BYTES + bu);
                Bh[pr * 2][0] = r4[0]; Bh[pr * 2][1] = r4[1];
                Bh[pr * 2 + 1][0] = r4[2]; Bh[pr * 2 + 1][1] = r4[3];
                ldsm4(r4, st + 3 * PLANE_BYTES + bu);
                Bl[pr * 2][0] = r4[0]; Bl[pr * 2][1] = r4[1];
                Bl[pr * 2 + 1][0] = r4[2]; Bl[pr * 2 + 1][1] = r4[3];
            }
            #pragma unroll
            for (int mt = 0; mt < 2; mt++)
                #pragma unroll
                for (int nt = 0; nt < 4; nt++) {
                    mma_f16(am[mt][nt], Ah[mt], Bh[nt]);
                    mma_f16(ac[mt][nt], Ah[mt], Bl[nt]);
                    mma_f16(ac[mt][nt], Al[mt], Bh[nt]);
                }
        }
    }
    __syncthreads();

    // epilogue
    float* srows = (float*)smem;
    float rsl[2], rsh[2];
    #pragma unroll
    for (int mt = 0; mt < 2; mt++) { rsl[mt] = 0.f; rsh[mt] = 0.f; }

    #pragma unroll
    for (int mt = 0; mt < 2; mt++) {
        const int rl = warp_m * 32 + mt * 16 + (lane >> 2);
        #pragma unroll
        for (int nt = 0; nt < 4; nt++) {
            const int gc = col0 + warp_n * 32 + nt * 8 + (lane & 3) * 2;
            float e0 = fast_exp(am[mt][nt][0] + ac[mt][nt][0] * LO_INV);
            float e1 = fast_exp(am[mt][nt][1] + ac[mt][nt][1] * LO_INV);
            float e2 = fast_exp(am[mt][nt][2] + ac[mt][nt][2] * LO_INV);
            float e3 = fast_exp(am[mt][nt][3] + ac[mt][nt][3] * LO_INV);
            if (gc >= MEM)     { e0 = 0.f; e2 = 0.f; }
            if (gc + 1 >= MEM) { e1 = 0.f; e3 = 0.f; }
            const int growl = row0 + rl;
            *(float2*)(g_E + (size_t)growl * MPAD + gc) = make_float2(e0, e1);
            *(float2*)(g_E + (size_t)(growl + 8) * MPAD + gc) = make_float2(e2, e3);
            rsl[mt] += e0 + e1;
            rsh[mt] += e2 + e3;
        }
    }
    #pragma unroll
    for (int mt = 0; mt < 2; mt++) {
        #pragma unroll
        for (int o = 1; o <= 2; o <<= 1) {
            rsl[mt] += __shfl_xor_sync(FULL_MASK, rsl[mt], o);
            rsh[mt] += __shfl_xor_sync(FULL_MASK, rsh[mt], o);
        }
    }
    if ((lane & 3) == 0) {
        #pragma unroll
        for (int mt = 0; mt < 2; mt++) {
            const int rl = warp_m * 32 + mt * 16 + (lane >> 2);
            srows[rl * 4 + warp_n] = rsl[mt];
            srows[(rl + 8) * 4 + warp_n] = rsh[mt];
        }
    }
    __syncthreads();
    if (tid < 128) {
        const float z = srows[tid * 4 + 0] + srows[tid * 4 + 1] +
                        srows[tid * 4 + 2] + srows[tid * 4 + 3];
        g_Zp[blockIdx.x * NROWS + row0 + tid] = z;
    }
}

// ---------------------------------------------------------------------------
// K2: per row (1 warp/row): E row staged in SMEM via cp.async (low regs ->
//     3 CTAs/SM), Z, threshold, survivor sum, att write, sparse out.
//     Each thread reads only the smem slots it loaded (per-thread wait OK).
// ---------------------------------------------------------------------------
__global__ void __launch_bounds__(256)
k_finish_r16(const float* __restrict__ w, float* __restrict__ out,
             float* __restrict__ att) {
    extern __shared__ __align__(16) float sE[];   // [8][2048]
    const int lane = threadIdx.x & 31;
    const int wid  = threadIdx.x >> 5;
    const int n    = blockIdx.x * 8 + wid;

    float* rowE = sE + wid * MPAD;
    const uint32_t srow = smem_u32(rowE);
    const float4* E4 = (const float4*)(g_E + (size_t)n * MPAD);

    // stage E row into smem (each thread loads its own 16 float4)
    #pragma unroll
    for (int it = 0; it < 16; it++) {
        const int i = lane + 32 * it;
        if (i < MEM / 4) {
            cpa16(srow + i * 16, E4 + i);
        } else {
            *(float4*)(rowE + i * 4) = make_float4(0.f, 0.f, 0.f, 0.f);
        }
    }
    cpa_commit();

    float Z = 0.f;
    #pragma unroll
    for (int j = 0; j < NMBLK; j++) Z += g_Zp[j * NROWS + n];
    const float t = LAMBDA * Z;

    cpa_wait<0>();

    // survivor sum
    float s = 0.f;
    #pragma unroll
    for (int it = 0; it < 16; it++) {
        float4 v = *(const float4*)(rowE + (lane + 32 * it) * 4);
        if (v.x > t) s += v.x;
        if (v.y > t) s += v.y;
        if (v.z > t) s += v.z;
        if (v.w > t) s += v.w;
    }
    #pragma unroll
    for (int o = 16; o; o >>= 1) s += __shfl_xor_sync(FULL_MASK, s, o);
    const float inv = (s > 0.f) ? (1.0f / s) : 0.f;

    float4* att4 = (float4*)(att + (size_t)n * MEM);
    float oacc[16];
    #pragma unroll
    for (int q = 0; q < 16; q++) oacc[q] = 0.f;

    #pragma unroll 1
    for (int it = 0; it < 16; it++) {
        const int i = lane + 32 * it;
        const bool active = (i < MEM / 4);
        float4 v = *(const float4*)(rowE + i * 4);
        float4 o;
        int m4 = 0;
        o.x = (v.x > t) ? v.x * inv : 0.f; if (v.x > t) m4 |= 1;
        o.y = (v.y > t) ? v.y * inv : 0.f; if (v.y > t) m4 |= 2;
        o.z = (v.z > t) ? v.z * inv : 0.f; if (v.z > t) m4 |= 4;
        o.w = (v.w > t) ? v.w * inv : 0.f; if (v.w > t) m4 |= 8;
        if (active) att4[i] = o;

        unsigned bal = __ballot_sync(FULL_MASK, m4 != 0);
        while (bal) {
            const int src = __ffs(bal) - 1;
            bal &= bal - 1;
            const int sm4 = __shfl_sync(FULL_MASK, m4, src);
            float av[4];
            av[0] = __shfl_sync(FULL_MASK, o.x, src);
            av[1] = __shfl_sync(FULL_MASK, o.y, src);
            av[2] = __shfl_sync(FULL_MASK, o.z, src);
            av[3] = __shfl_sync(FULL_MASK, o.w, src);
            const int mbase = 4 * (src + 32 * it);
            #pragma unroll
            for (int j = 0; j < 4; j++) {
                if (sm4 & (1 << j)) {
                    const float* wr = w + (size_t)(mbase + j) * KDIM;
                    const float a = av[j];
                    #pragma unroll
                    for (int q = 0; q < 16; q++)
                        oacc[q] += a * wr[lane + 32 * q];
                }
            }
        }
    }

    float* orow = out + (size_t)n * KDIM;
    #pragma unroll
    for (int q = 0; q < 16; q++) orow[lane + 32 * q] = oacc[q];
}

// ---------------------------------------------------------------------------
extern "C" void kernel_launch(void* const* d_in, const int* in_sizes, int n_in,
                              void* d_out, int out_size) {
    (void)in_sizes; (void)n_in; (void)out_size;
    const float* x = (const float*)d_in[0];
    const float* w = (const float*)d_in[1];
    float* out = (float*)d_out;
    float* att = (float*)d_out + (size_t)NROWS * KDIM;

    cudaFuncSetAttribute(k_gemm_mma_r16,
                         cudaFuncAttributeMaxDynamicSharedMemorySize, SMEM_TOTAL);
    cudaFuncSetAttribute(k_finish_r16,
                         cudaFuncAttributeMaxDynamicSharedMemorySize, FIN_SMEM);

    k_prep_r16<<<(NROWS * KDIM / 4) / 256, 256>>>(x, w);
    k_gemm_mma_r16<<<dim3(NMBLK, NROWS / BM), 512, SMEM_TOTAL>>>();
    k_finish_r16<<<NROWS / 8, 256, FIN_SMEM>>>(w, out, att);
}